// round 2
// baseline (speedup 1.0000x reference)
#include <cuda_runtime.h>
#include <math.h>

#define N_TS 8192
#define N_LC 12288
#define NB   64
#define TSB  128     // TS points per graph
#define LCB  192     // LC points per graph
#define H    16
#define KNN  16

// -------- scratch (no allocs allowed; __device__ globals) --------
__device__ float g_ts_enc[N_TS * H];
__device__ float g_lc_enc[N_LC * H];
__device__ float g_u_ts [N_TS * H];   // conv2 dst precomp: b + x@(Wt-Wb)
__device__ float g_u_lc [N_LC * H];   // conv1 dst precomp
__device__ float g_v_lc [N_LC * H];   // conv1/2 src precomp: x@Wb
__device__ float g_f1  [N_LC * H];    // feats1
__device__ float g_f2  [N_TS * H];    // feats2
__device__ float g_v3  [N_LC * H];    // feats1@Wb
__device__ float g_u3  [N_TS * H];    // b + feats2@(Wt-Wb)
__device__ float g_f3  [N_TS * H];    // feats3

__device__ __forceinline__ float eluf(float x) { return x > 0.f ? x : expm1f(x); }

// ==================== K1: encoders + u/v precompute ====================
__global__ void k_encode(const float* __restrict__ x_ts, const float* __restrict__ x_lc,
                         const float* __restrict__ tw1, const float* __restrict__ tb1,
                         const float* __restrict__ tw2, const float* __restrict__ tb2,
                         const float* __restrict__ lw1, const float* __restrict__ lb1,
                         const float* __restrict__ lw2, const float* __restrict__ lb2,
                         const float* __restrict__ cw,  const float* __restrict__ cb)
{
    int tid = blockIdx.x * blockDim.x + threadIdx.x;
    if (tid < N_TS) {
        float x[6], h1[H], e[H];
        #pragma unroll
        for (int i = 0; i < 6; i++) x[i] = __ldg(&x_ts[tid * 6 + i]);
        #pragma unroll
        for (int o = 0; o < H; o++) {
            float s = __ldg(&tb1[o]);
            #pragma unroll
            for (int i = 0; i < 6; i++) s += x[i] * __ldg(&tw1[i * H + o]);
            h1[o] = eluf(s);
        }
        #pragma unroll
        for (int o = 0; o < H; o++) {
            float s = __ldg(&tb2[o]);
            #pragma unroll
            for (int i = 0; i < H; i++) s += h1[i] * __ldg(&tw2[i * H + o]);
            e[o] = eluf(s);
            g_ts_enc[tid * H + o] = e[o];
        }
        #pragma unroll
        for (int o = 0; o < H; o++) {
            float s = __ldg(&cb[o]);
            #pragma unroll
            for (int i = 0; i < H; i++)
                s += e[i] * (__ldg(&cw[i * H + o]) - __ldg(&cw[(H + i) * H + o]));
            g_u_ts[tid * H + o] = s;
        }
    } else if (tid < N_TS + N_LC) {
        int id = tid - N_TS;
        float x[5], h1[H], e[H];
        #pragma unroll
        for (int i = 0; i < 5; i++) x[i] = __ldg(&x_lc[id * 5 + i]);
        #pragma unroll
        for (int o = 0; o < H; o++) {
            float s = __ldg(&lb1[o]);
            #pragma unroll
            for (int i = 0; i < 5; i++) s += x[i] * __ldg(&lw1[i * H + o]);
            h1[o] = eluf(s);
        }
        #pragma unroll
        for (int o = 0; o < H; o++) {
            float s = __ldg(&lb2[o]);
            #pragma unroll
            for (int i = 0; i < H; i++) s += h1[i] * __ldg(&lw2[i * H + o]);
            e[o] = eluf(s);
            g_lc_enc[id * H + o] = e[o];
        }
        #pragma unroll
        for (int o = 0; o < H; o++) {
            float su = __ldg(&cb[o]);
            float sv = 0.f;
            #pragma unroll
            for (int i = 0; i < H; i++) {
                float wt = __ldg(&cw[i * H + o]);
                float wb = __ldg(&cw[(H + i) * H + o]);
                su += e[i] * (wt - wb);
                sv += e[i] * wb;
            }
            g_u_lc[id * H + o] = su;
            g_v_lc[id * H + o] = sv;
        }
    }
}

// ==================== edge-conv core ====================
struct __align__(16) ConvSmem {
    float enc[LCB * H];   // src features
    float v  [LCB * H];   // src message precomp
    float nrm[LCB];       // src squared norms
    float w  [2 * H * H]; // conv_w (for fused post-transform)
    float b  [H];         // conv_b
};

// 64 threads; each handles exactly one dst row (chunks are always full 64).
__device__ __forceinline__ void conv_block(const float* __restrict__ src_enc,
                                           const float* __restrict__ src_v,
                                           int n_src,
                                           const float* __restrict__ dst_enc,
                                           const float* __restrict__ dst_u,
                                           float* __restrict__ out,
                                           ConvSmem& s, float fOut[H])
{
    int t = threadIdx.x;
    // stage src enc + v + norms
    for (int r = t; r < n_src; r += 64) {
        float4* de = (float4*)&s.enc[r * H];
        const float4* ge = (const float4*)&src_enc[r * H];
        float nrm = 0.f;
        #pragma unroll
        for (int q = 0; q < 4; q++) {
            float4 p = ge[q]; de[q] = p;
            nrm += p.x * p.x + p.y * p.y + p.z * p.z + p.w * p.w;
        }
        s.nrm[r] = nrm;
        float4* dv = (float4*)&s.v[r * H];
        const float4* gv = (const float4*)&src_v[r * H];
        #pragma unroll
        for (int q = 0; q < 4; q++) dv[q] = gv[q];
    }
    __syncthreads();

    // dst row into registers
    float xi[H];
    {
        const float4* gd = (const float4*)&dst_enc[t * H];
        #pragma unroll
        for (int q = 0; q < 4; q++) {
            float4 p = gd[q];
            xi[4 * q + 0] = p.x; xi[4 * q + 1] = p.y; xi[4 * q + 2] = p.z; xi[4 * q + 3] = p.w;
        }
    }
    float nd = 0.f;
    #pragma unroll
    for (int i = 0; i < H; i++) nd += xi[i] * xi[i];

    // kNN: sorted insertion, strict < keeps lowest-index on ties (matches top_k)
    float bd[KNN]; int bi[KNN];
    #pragma unroll
    for (int k = 0; k < KNN; k++) { bd[k] = 1e30f; bi[k] = 0; }

    const float4* e4 = (const float4*)s.enc;
    #pragma unroll 2
    for (int j = 0; j < n_src; j++) {
        float4 p0 = e4[j * 4 + 0], p1 = e4[j * 4 + 1], p2 = e4[j * 4 + 2], p3 = e4[j * 4 + 3];
        float d0 = xi[0]  * p0.x + xi[1]  * p0.y + xi[2]  * p0.z + xi[3]  * p0.w;
        float d1 = xi[4]  * p1.x + xi[5]  * p1.y + xi[6]  * p1.z + xi[7]  * p1.w;
        float d2 = xi[8]  * p2.x + xi[9]  * p2.y + xi[10] * p2.z + xi[11] * p2.w;
        float d3 = xi[12] * p3.x + xi[13] * p3.y + xi[14] * p3.z + xi[15] * p3.w;
        float dot = (d0 + d1) + (d2 + d3);
        float dist = (nd - 2.f * dot) + s.nrm[j];
        if (dist < bd[KNN - 1]) {
            float v = dist; int vi = j;
            #pragma unroll
            for (int k = 0; k < KNN; k++) {
                float od = bd[k]; int oi = bi[k];
                bool lt = v < od;
                bd[k] = lt ? v  : od;
                bi[k] = lt ? vi : oi;
                v  = lt ? od : v;
                vi = lt ? oi : vi;
            }
        }
    }

    // messages: elu(u + v_j), max over K
    float uu[H];
    {
        const float4* gu = (const float4*)&dst_u[t * H];
        #pragma unroll
        for (int q = 0; q < 4; q++) {
            float4 p = gu[q];
            uu[4 * q + 0] = p.x; uu[4 * q + 1] = p.y; uu[4 * q + 2] = p.z; uu[4 * q + 3] = p.w;
        }
    }
    float acc[H];
    #pragma unroll
    for (int h = 0; h < H; h++) acc[h] = -1e30f;
    const float4* v4 = (const float4*)s.v;
    #pragma unroll
    for (int k = 0; k < KNN; k++) {
        int j = bi[k];
        float4 p0 = v4[j * 4 + 0], p1 = v4[j * 4 + 1], p2 = v4[j * 4 + 2], p3 = v4[j * 4 + 3];
        acc[0]  = fmaxf(acc[0],  eluf(uu[0]  + p0.x));
        acc[1]  = fmaxf(acc[1],  eluf(uu[1]  + p0.y));
        acc[2]  = fmaxf(acc[2],  eluf(uu[2]  + p0.z));
        acc[3]  = fmaxf(acc[3],  eluf(uu[3]  + p0.w));
        acc[4]  = fmaxf(acc[4],  eluf(uu[4]  + p1.x));
        acc[5]  = fmaxf(acc[5],  eluf(uu[5]  + p1.y));
        acc[6]  = fmaxf(acc[6],  eluf(uu[6]  + p1.z));
        acc[7]  = fmaxf(acc[7],  eluf(uu[7]  + p1.w));
        acc[8]  = fmaxf(acc[8],  eluf(uu[8]  + p2.x));
        acc[9]  = fmaxf(acc[9],  eluf(uu[9]  + p2.y));
        acc[10] = fmaxf(acc[10], eluf(uu[10] + p2.z));
        acc[11] = fmaxf(acc[11], eluf(uu[11] + p2.w));
        acc[12] = fmaxf(acc[12], eluf(uu[12] + p3.x));
        acc[13] = fmaxf(acc[13], eluf(uu[13] + p3.y));
        acc[14] = fmaxf(acc[14], eluf(uu[14] + p3.z));
        acc[15] = fmaxf(acc[15], eluf(uu[15] + p3.w));
    }
    float4* go = (float4*)&out[t * H];
    #pragma unroll
    for (int q = 0; q < 4; q++) {
        float4 p;
        p.x = acc[4 * q + 0]; p.y = acc[4 * q + 1]; p.z = acc[4 * q + 2]; p.w = acc[4 * q + 3];
        go[q] = p;
    }
    #pragma unroll
    for (int h = 0; h < H; h++) fOut[h] = acc[h];
}

// ==================== K2: conv1 + conv2 (+ fused u3/v3) ====================
__global__ void k_conv12(const float* __restrict__ cw, const float* __restrict__ cb)
{
    __shared__ ConvSmem s;
    int t = threadIdx.x, bid = blockIdx.x;
    for (int i = t; i < 2 * H * H; i += 64) s.w[i] = __ldg(&cw[i]);
    if (t < H) s.b[t] = __ldg(&cb[t]);
    float f[H];
    if (bid < NB * 3) {                 // conv1: LC -> LC
        int batch = bid / 3, chunk = bid % 3;
        int drow = batch * LCB + chunk * 64;
        conv_block(g_lc_enc + batch * LCB * H, g_v_lc + batch * LCB * H, LCB,
                   g_lc_enc + drow * H, g_u_lc + drow * H, g_f1 + drow * H, s, f);
        // v3 = f @ Wb
        int row = drow + t;
        #pragma unroll
        for (int o = 0; o < H; o++) {
            float sum = 0.f;
            #pragma unroll
            for (int i = 0; i < H; i++) sum += f[i] * s.w[(H + i) * H + o];
            g_v3[row * H + o] = sum;
        }
    } else {                            // conv2: LC -> TS
        int q = bid - NB * 3;
        int batch = q / 2, chunk = q % 2;
        int drow = batch * TSB + chunk * 64;
        conv_block(g_lc_enc + batch * LCB * H, g_v_lc + batch * LCB * H, LCB,
                   g_ts_enc + drow * H, g_u_ts + drow * H, g_f2 + drow * H, s, f);
        // u3 = b + f @ (Wt - Wb)
        int row = drow + t;
        #pragma unroll
        for (int o = 0; o < H; o++) {
            float sum = s.b[o];
            #pragma unroll
            for (int i = 0; i < H; i++) sum += f[i] * (s.w[i * H + o] - s.w[(H + i) * H + o]);
            g_u3[row * H + o] = sum;
        }
    }
}

// ==================== K3: conv3 ====================
__global__ void k_conv3()
{
    __shared__ ConvSmem s;
    int bid = blockIdx.x;
    int batch = bid / 2, chunk = bid % 2;
    int drow = batch * TSB + chunk * 64;
    float f[H];
    conv_block(g_f1 + batch * LCB * H, g_v3 + batch * LCB * H, LCB,
               g_f2 + drow * H, g_u3 + drow * H, g_f3 + drow * H, s, f);
}

// ==================== K4: mean pool + head ====================
__global__ void k_final(const float* __restrict__ w1, const float* __restrict__ b1,
                        const float* __restrict__ w2, const float* __restrict__ b2,
                        const float* __restrict__ w3, const float* __restrict__ b3,
                        const float* __restrict__ w4, const float* __restrict__ b4,
                        const float* __restrict__ w5, const float* __restrict__ b5,
                        float* __restrict__ out, int out_size)
{
    __shared__ float red[TSB * H];
    __shared__ float pooled[H];
    __shared__ float h1[64], h2[32], h3[8], h4[4];
    int b = blockIdx.x, t = threadIdx.x;

    const float4* g = (const float4*)&g_f3[(b * TSB + t) * H];
    float4* r4 = (float4*)&red[t * H];
    #pragma unroll
    for (int q = 0; q < 4; q++) r4[q] = g[q];
    __syncthreads();

    float4* rr = (float4*)red;
    for (int sft = 64; sft > 0; sft >>= 1) {
        if (t < sft) {
            #pragma unroll
            for (int q = 0; q < 4; q++) {
                float4 a = rr[t * 4 + q], c = rr[(t + sft) * 4 + q];
                a.x += c.x; a.y += c.y; a.z += c.z; a.w += c.w;
                rr[t * 4 + q] = a;
            }
        }
        __syncthreads();
    }
    if (t < H) pooled[t] = red[t] * (1.f / (float)TSB);
    __syncthreads();

    if (t < 64) {
        float sv = __ldg(&b1[t]);
        #pragma unroll
        for (int i = 0; i < H; i++) sv += pooled[i] * __ldg(&w1[i * 64 + t]);
        h1[t] = eluf(sv);
    }
    __syncthreads();
    if (t < 32) {
        float sv = __ldg(&b2[t]);
        #pragma unroll
        for (int i = 0; i < 64; i++) sv += h1[i] * __ldg(&w2[i * 32 + t]);
        h2[t] = eluf(sv);
    }
    __syncthreads();
    if (t < 8) {
        float sv = __ldg(&b3[t]);
        #pragma unroll
        for (int i = 0; i < 32; i++) sv += h2[i] * __ldg(&w3[i * 8 + t]);
        h3[t] = eluf(sv);
    }
    __syncthreads();
    if (t < 4) {
        float sv = __ldg(&b4[t]);
        #pragma unroll
        for (int i = 0; i < 8; i++) sv += h3[i] * __ldg(&w4[i * 4 + t]);
        h4[t] = eluf(sv);
    }
    __syncthreads();
    if (t == 0) {
        float sv = __ldg(&b5[0]);
        #pragma unroll
        for (int i = 0; i < 4; i++) sv += h4[i] * __ldg(&w5[i]);
        if (b < out_size) out[b] = sv;
    }
    // batch_out tail (arange(64)) if the harness concatenated both outputs
    if (b == 0 && t < 64) {
        int idx = NB + t;
        if (idx < out_size) out[idx] = (float)t;
    }
}

// ==================== launch ====================
extern "C" void kernel_launch(void* const* d_in, const int* in_sizes, int n_in,
                              void* d_out, int out_size)
{
    const float* x_ts = (const float*)d_in[0];
    const float* x_lc = (const float*)d_in[1];
    // d_in[2], d_in[3]: batch indices (contiguous repeats; implied by index math)
    const float* tw1 = (const float*)d_in[4];
    const float* tb1 = (const float*)d_in[5];
    const float* tw2 = (const float*)d_in[6];
    const float* tb2 = (const float*)d_in[7];
    const float* lw1 = (const float*)d_in[8];
    const float* lb1 = (const float*)d_in[9];
    const float* lw2 = (const float*)d_in[10];
    const float* lb2 = (const float*)d_in[11];
    const float* cw  = (const float*)d_in[12];
    const float* cb  = (const float*)d_in[13];
    const float* w1  = (const float*)d_in[14];
    const float* b1  = (const float*)d_in[15];
    const float* w2  = (const float*)d_in[16];
    const float* b2  = (const float*)d_in[17];
    const float* w3  = (const float*)d_in[18];
    const float* b3  = (const float*)d_in[19];
    const float* w4  = (const float*)d_in[20];
    const float* b4  = (const float*)d_in[21];
    const float* w5  = (const float*)d_in[22];
    const float* b5  = (const float*)d_in[23];

    k_encode<<<(N_TS + N_LC + 127) / 128, 128>>>(x_ts, x_lc, tw1, tb1, tw2, tb2,
                                                 lw1, lb1, lw2, lb2, cw, cb);
    k_conv12<<<NB * 3 + NB * 2, 64>>>(cw, cb);
    k_conv3<<<NB * 2, 64>>>();
    k_final<<<NB, 128>>>(w1, b1, w2, b2, w3, b3, w4, b4, w5, b5,
                         (float*)d_out, out_size);
}

// round 3
// speedup vs baseline: 1.4750x; 1.4750x over previous
#include <cuda_runtime.h>
#include <math.h>

#define N_TS 8192
#define N_LC 12288
#define NB   64
#define TSB  128     // TS points per graph
#define LCB  192     // LC points per graph
#define H    16
#define KNN  16

__device__ __forceinline__ float eluf(float x) { return x > 0.f ? x : expm1f(x); }

struct __align__(16) Smem {
    float enc[LCB * H];      // src features (phase B: lc_enc, phase D: feats1)
    float v  [LCB * H];      // src message precomp (v_lc, then v3)
    float nrm[LCB];          // src squared norms
    float w  [2 * H * H];    // conv_w
    float b  [H];            // conv_b
    float exch[128 * 33];    // pair exchange (padded rows to kill bank conflicts)
};

// sorted-insert into a 16-deep ascending list; strict < keeps earliest index on ties
__device__ __forceinline__ void ins16(float (&bd)[KNN], int (&bi)[KNN], float v, int vi)
{
    if (v < bd[KNN - 1]) {
        #pragma unroll
        for (int k = 0; k < KNN; k++) {
            float od = bd[k]; int oi = bi[k];
            bool lt = v < od;
            bd[k] = lt ? v  : od;
            bi[k] = lt ? vi : oi;
            v  = lt ? od : v;
            vi = lt ? oi : vi;
        }
    }
}

__device__ __forceinline__ float dist16(const float (&xi)[H], const float4* __restrict__ e4,
                                        float nd, float nj, int j)
{
    float4 p0 = e4[j * 4 + 0], p1 = e4[j * 4 + 1], p2 = e4[j * 4 + 2], p3 = e4[j * 4 + 3];
    float d0 = xi[0]  * p0.x + xi[1]  * p0.y + xi[2]  * p0.z + xi[3]  * p0.w;
    float d1 = xi[4]  * p1.x + xi[5]  * p1.y + xi[6]  * p1.z + xi[7]  * p1.w;
    float d2 = xi[8]  * p2.x + xi[9]  * p2.y + xi[10] * p2.z + xi[11] * p2.w;
    float d3 = xi[12] * p3.x + xi[13] * p3.y + xi[14] * p3.z + xi[15] * p3.w;
    float dot = (d0 + d1) + (d2 + d3);
    return (nd - 2.f * dot) + nj;
}

// max of v_j over the 16 selected neighbors (elu deferred by monotonicity)
__device__ __forceinline__ void maxv16(const float4* __restrict__ v4, const int (&nb)[KNN],
                                       float (&mv)[H])
{
    #pragma unroll
    for (int h = 0; h < H; h++) mv[h] = -1e30f;
    #pragma unroll
    for (int k = 0; k < KNN; k++) {
        int j = nb[k];
        float4 p0 = v4[j * 4 + 0], p1 = v4[j * 4 + 1], p2 = v4[j * 4 + 2], p3 = v4[j * 4 + 3];
        mv[0]  = fmaxf(mv[0],  p0.x); mv[1]  = fmaxf(mv[1],  p0.y);
        mv[2]  = fmaxf(mv[2],  p0.z); mv[3]  = fmaxf(mv[3],  p0.w);
        mv[4]  = fmaxf(mv[4],  p1.x); mv[5]  = fmaxf(mv[5],  p1.y);
        mv[6]  = fmaxf(mv[6],  p1.z); mv[7]  = fmaxf(mv[7],  p1.w);
        mv[8]  = fmaxf(mv[8],  p2.x); mv[9]  = fmaxf(mv[9],  p2.y);
        mv[10] = fmaxf(mv[10], p2.z); mv[11] = fmaxf(mv[11], p2.w);
        mv[12] = fmaxf(mv[12], p3.x); mv[13] = fmaxf(mv[13], p3.y);
        mv[14] = fmaxf(mv[14], p3.z); mv[15] = fmaxf(mv[15], p3.w);
    }
}

__global__ __launch_bounds__(320, 1)
void k_fused(const float* __restrict__ x_ts, const float* __restrict__ x_lc,
             const float* __restrict__ tw1, const float* __restrict__ tb1,
             const float* __restrict__ tw2, const float* __restrict__ tb2,
             const float* __restrict__ lw1, const float* __restrict__ lb1,
             const float* __restrict__ lw2, const float* __restrict__ lb2,
             const float* __restrict__ cw,  const float* __restrict__ cb,
             const float* __restrict__ w1,  const float* __restrict__ b1,
             const float* __restrict__ w2,  const float* __restrict__ b2,
             const float* __restrict__ w3,  const float* __restrict__ b3,
             const float* __restrict__ w4,  const float* __restrict__ b4,
             const float* __restrict__ w5,  const float* __restrict__ b5,
             float* __restrict__ out, int out_size)
{
    __shared__ Smem s;
    const int bId = blockIdx.x;
    const int t = threadIdx.x;
    const bool isTS = t < TSB;            // threads 0..127: TS dst, 128..319: LC
    const int lcRow = t - TSB;            // 0..191 for LC threads

    // stage conv weights
    for (int i = t; i < 2 * H * H; i += 320) s.w[i] = __ldg(&cw[i]);
    if (t < H) s.b[t] = __ldg(&cb[t]);
    __syncthreads();

    // ---------------- Phase A: encoders + u/v precompute ----------------
    float e[H];   // encoded feature (xi for first conv)
    float u[H];   // dst precomp: b + e@(Wt-Wb)
    if (isTS) {
        float x[6], h1[H];
        const float* xr = &x_ts[(bId * TSB + t) * 6];
        #pragma unroll
        for (int i = 0; i < 6; i++) x[i] = __ldg(&xr[i]);
        #pragma unroll
        for (int o = 0; o < H; o++) {
            float sv = __ldg(&tb1[o]);
            #pragma unroll
            for (int i = 0; i < 6; i++) sv += x[i] * __ldg(&tw1[i * H + o]);
            h1[o] = eluf(sv);
        }
        #pragma unroll
        for (int o = 0; o < H; o++) {
            float sv = __ldg(&tb2[o]);
            #pragma unroll
            for (int i = 0; i < H; i++) sv += h1[i] * __ldg(&tw2[i * H + o]);
            e[o] = eluf(sv);
        }
        #pragma unroll
        for (int o = 0; o < H; o++) {
            float su = s.b[o];
            #pragma unroll
            for (int i = 0; i < H; i++)
                su += e[i] * (s.w[i * H + o] - s.w[(H + i) * H + o]);
            u[o] = su;
        }
    } else {
        float x[5], h1[H];
        const float* xr = &x_lc[(bId * LCB + lcRow) * 5];
        #pragma unroll
        for (int i = 0; i < 5; i++) x[i] = __ldg(&xr[i]);
        #pragma unroll
        for (int o = 0; o < H; o++) {
            float sv = __ldg(&lb1[o]);
            #pragma unroll
            for (int i = 0; i < 5; i++) sv += x[i] * __ldg(&lw1[i * H + o]);
            h1[o] = eluf(sv);
        }
        #pragma unroll
        for (int o = 0; o < H; o++) {
            float sv = __ldg(&lb2[o]);
            #pragma unroll
            for (int i = 0; i < H; i++) sv += h1[i] * __ldg(&lw2[i * H + o]);
            e[o] = eluf(sv);
        }
        float nrm = 0.f;
        #pragma unroll
        for (int o = 0; o < H; o++) nrm += e[o] * e[o];
        #pragma unroll
        for (int o = 0; o < H; o++) {
            float su = s.b[o], sv = 0.f;
            #pragma unroll
            for (int i = 0; i < H; i++) {
                float wt = s.w[i * H + o], wb = s.w[(H + i) * H + o];
                su += e[i] * (wt - wb);
                sv += e[i] * wb;
            }
            u[o] = su;
            s.v[lcRow * H + o] = sv;
        }
        #pragma unroll
        for (int o = 0; o < H; o++) s.enc[lcRow * H + o] = e[o];
        s.nrm[lcRow] = nrm;
    }
    __syncthreads();

    // ---------------- Phase B: conv1 (LC dst) + conv2 (TS dst) ----------------
    float f[H];   // conv output for this dst
    {
        float nd = 0.f;
        #pragma unroll
        for (int i = 0; i < H; i++) nd += e[i] * e[i];

        float bdA[KNN], bdB[KNN]; int biA[KNN], biB[KNN];
        #pragma unroll
        for (int k = 0; k < KNN; k++) { bdA[k] = 1e30f; biA[k] = 0; bdB[k] = 1e30f; biB[k] = 96; }

        const float4* e4 = (const float4*)s.enc;
        for (int j = 0; j < 96; j++) {
            float dA = dist16(e, e4, nd, s.nrm[j], j);
            float dB = dist16(e, e4, nd, s.nrm[j + 96], j + 96);
            ins16(bdA, biA, dA, j);
            ins16(bdB, biB, dB, j + 96);
        }
        // merge two sorted 16-lists into the (unordered) set of 16 smallest
        int nb[KNN];
        #pragma unroll
        for (int k = 0; k < KNN; k++)
            nb[k] = (bdB[KNN - 1 - k] < bdA[k]) ? biB[KNN - 1 - k] : biA[k];

        float mv[H];
        maxv16((const float4*)s.v, nb, mv);
        #pragma unroll
        for (int h = 0; h < H; h++) f[h] = eluf(u[h] + mv[h]);
    }

    // ---------------- Phase C: conv3 precomp (u3 for TS, v3+nrm for LC) ----------------
    float u3[H];          // TS only
    float v3[H], nrmf;    // LC only
    if (isTS) {
        #pragma unroll
        for (int o = 0; o < H; o++) {
            float sv = s.b[o];
            #pragma unroll
            for (int i = 0; i < H; i++)
                sv += f[i] * (s.w[i * H + o] - s.w[(H + i) * H + o]);
            u3[o] = sv;
        }
    } else {
        nrmf = 0.f;
        #pragma unroll
        for (int i = 0; i < H; i++) nrmf += f[i] * f[i];
        #pragma unroll
        for (int o = 0; o < H; o++) {
            float sv = 0.f;
            #pragma unroll
            for (int i = 0; i < H; i++) sv += f[i] * s.w[(H + i) * H + o];
            v3[o] = sv;
        }
    }
    __syncthreads();   // everyone done reading enc/v/nrm of round 1

    if (!isTS) {       // stage feats1 / v3 / norms for conv3
        #pragma unroll
        for (int o = 0; o < H; o++) {
            s.enc[lcRow * H + o] = f[o];
            s.v[lcRow * H + o]   = v3[o];
        }
        s.nrm[lcRow] = nrmf;
    }
    // owners publish their query (feats2) for the helper thread
    if (isTS) {
        #pragma unroll
        for (int o = 0; o < H; o++) s.exch[t * 33 + o] = f[o];
    }
    __syncthreads();

    // ---------------- Phase D: conv3 (TS dst, pair-split scan) ----------------
    const bool owner  = t < 128;
    const bool helper = (t >= 128) && (t < 256);
    float bdA[KNN]; int biA[KNN];
    if (owner || helper) {
        const int d = owner ? t : (t - 128);
        float xi[H];
        if (owner) {
            #pragma unroll
            for (int i = 0; i < H; i++) xi[i] = f[i];
        } else {
            #pragma unroll
            for (int i = 0; i < H; i++) xi[i] = s.exch[d * 33 + i];
        }
        float nd = 0.f;
        #pragma unroll
        for (int i = 0; i < H; i++) nd += xi[i] * xi[i];

        #pragma unroll
        for (int k = 0; k < KNN; k++) { bdA[k] = 1e30f; biA[k] = owner ? 0 : 96; }

        const float4* e4 = (const float4*)s.enc;
        const int base = owner ? 0 : 96;
        for (int j = 0; j < 96; j++) {
            int jj = base + j;
            float dd = dist16(xi, e4, nd, s.nrm[jj], jj);
            ins16(bdA, biA, dd, jj);
        }
    }
    if (helper) {   // publish sorted list
        const int d = t - 128;
        #pragma unroll
        for (int k = 0; k < KNN; k++) {
            s.exch[d * 33 + k]       = bdA[k];
            s.exch[d * 33 + 16 + k]  = __int_as_float(biA[k]);
        }
    }
    __syncthreads();

    float f3[H];
    if (owner) {
        int nb[KNN];
        #pragma unroll
        for (int k = 0; k < KNN; k++) {
            float pd = s.exch[t * 33 + (KNN - 1 - k)];
            int   pi = __float_as_int(s.exch[t * 33 + 16 + (KNN - 1 - k)]);
            nb[k] = (pd < bdA[k]) ? pi : biA[k];
        }
        float mv[H];
        maxv16((const float4*)s.v, nb, mv);
        #pragma unroll
        for (int h = 0; h < H; h++) f3[h] = eluf(u3[h] + mv[h]);
    }
    __syncthreads();   // done reading s.enc; reuse it for pooling

    // ---------------- Phase E: mean pool + head ----------------
    if (owner) {
        #pragma unroll
        for (int h = 0; h < H; h++) s.enc[t * H + h] = f3[h];
    }
    __syncthreads();

    float4* rr = (float4*)s.enc;
    for (int sft = 64; sft > 0; sft >>= 1) {
        if (t < sft) {
            #pragma unroll
            for (int q = 0; q < 4; q++) {
                float4 a = rr[t * 4 + q], c = rr[(t + sft) * 4 + q];
                a.x += c.x; a.y += c.y; a.z += c.z; a.w += c.w;
                rr[t * 4 + q] = a;
            }
        }
        __syncthreads();
    }
    __shared__ float pooled[H];
    __shared__ float h1s[64], h2s[32], h3s[8], h4s[4];
    if (t < H) pooled[t] = s.enc[t] * (1.f / (float)TSB);
    __syncthreads();

    if (t < 64) {
        float sv = __ldg(&b1[t]);
        #pragma unroll
        for (int i = 0; i < H; i++) sv += pooled[i] * __ldg(&w1[i * 64 + t]);
        h1s[t] = eluf(sv);
    }
    __syncthreads();
    if (t < 32) {
        float sv = __ldg(&b2[t]);
        #pragma unroll
        for (int i = 0; i < 64; i++) sv += h1s[i] * __ldg(&w2[i * 32 + t]);
        h2s[t] = eluf(sv);
    }
    __syncthreads();
    if (t < 8) {
        float sv = __ldg(&b3[t]);
        #pragma unroll
        for (int i = 0; i < 32; i++) sv += h2s[i] * __ldg(&w3[i * 8 + t]);
        h3s[t] = eluf(sv);
    }
    __syncthreads();
    if (t < 4) {
        float sv = __ldg(&b4[t]);
        #pragma unroll
        for (int i = 0; i < 8; i++) sv += h3s[i] * __ldg(&w4[i * 4 + t]);
        h4s[t] = eluf(sv);
    }
    __syncthreads();
    if (t == 0) {
        float sv = __ldg(&b5[0]);
        #pragma unroll
        for (int i = 0; i < 4; i++) sv += h4s[i] * __ldg(&w5[i]);
        if (bId < out_size) out[bId] = sv;
    }
    // batch_out tail (arange(64)) if harness concatenated both outputs
    if (bId == 0 && t < NB) {
        int idx = NB + t;
        if (idx < out_size) out[idx] = (float)t;
    }
}

extern "C" void kernel_launch(void* const* d_in, const int* in_sizes, int n_in,
                              void* d_out, int out_size)
{
    const float* x_ts = (const float*)d_in[0];
    const float* x_lc = (const float*)d_in[1];
    const float* tw1 = (const float*)d_in[4];
    const float* tb1 = (const float*)d_in[5];
    const float* tw2 = (const float*)d_in[6];
    const float* tb2 = (const float*)d_in[7];
    const float* lw1 = (const float*)d_in[8];
    const float* lb1 = (const float*)d_in[9];
    const float* lw2 = (const float*)d_in[10];
    const float* lb2 = (const float*)d_in[11];
    const float* cw  = (const float*)d_in[12];
    const float* cb  = (const float*)d_in[13];
    const float* w1  = (const float*)d_in[14];
    const float* b1  = (const float*)d_in[15];
    const float* w2  = (const float*)d_in[16];
    const float* b2  = (const float*)d_in[17];
    const float* w3  = (const float*)d_in[18];
    const float* b3  = (const float*)d_in[19];
    const float* w4  = (const float*)d_in[20];
    const float* b4  = (const float*)d_in[21];
    const float* w5  = (const float*)d_in[22];
    const float* b5  = (const float*)d_in[23];

    k_fused<<<NB, 320>>>(x_ts, x_lc, tw1, tb1, tw2, tb2, lw1, lb1, lw2, lb2,
                         cw, cb, w1, b1, w2, b2, w3, b3, w4, b4, w5, b5,
                         (float*)d_out, out_size);
}